// round 1
// baseline (speedup 1.0000x reference)
#include <cuda_runtime.h>
#include <cuda_bf16.h>
#include <cfloat>

// Problem constants
#define NROWS   16000      // B*T = 16*1000
#define NBANDS  64
#define HIDDEN  512
#define LATENT  256
#define GRP     8
#define GD      32
#define KCB     1024

// Scratch (allocation-free: __device__ globals)
__device__ float g_hidden[NROWS * HIDDEN];      // 32 MB scratch for both MLP hiddens
__device__ float g_loss_part[1024];             // per-block VQ loss partials (125*8 = 1000 used)

// ---------------------------------------------------------------------------
// Tiled SGEMM with fused bias (+ optional ReLU).  C[M,N] = act(A[M,K]@B[K,N]+bias)
// BM=128, BN=64, BK=16, 256 threads, 8x4 per-thread micro-tile.
// Assumes M%BM==0, N%BN==0, K%BK==0 (true for all 4 calls here).
// ---------------------------------------------------------------------------
template<int BM, int BN, int BK, int TM, int TN, bool RELU>
__global__ __launch_bounds__(256) void sgemm_bias(
    const float* __restrict__ A, const float* __restrict__ B,
    const float* __restrict__ bias, float* __restrict__ C,
    int M, int N, int K)
{
    constexpr int THREADS = (BM / TM) * (BN / TN);   // 256
    __shared__ float As[BK][BM + 4];                 // A transposed: [k][m]
    __shared__ float Bs[BK][BN + 4];                 // B natural:    [k][n]

    const int tid = threadIdx.x;
    const int tx  = tid % (BN / TN);   // 0..15
    const int ty  = tid / (BN / TN);   // 0..15
    const int m0  = blockIdx.y * BM;
    const int n0  = blockIdx.x * BN;

    float acc[TM][TN];
    #pragma unroll
    for (int i = 0; i < TM; i++)
        #pragma unroll
        for (int j = 0; j < TN; j++) acc[i][j] = 0.0f;

    for (int k0 = 0; k0 < K; k0 += BK) {
        // Load A tile (BM x BK) as float4 along K, store transposed
        #pragma unroll
        for (int f = tid; f < BM * BK / 4; f += THREADS) {
            int r  = f / (BK / 4);
            int kq = f % (BK / 4);
            float4 v = *(const float4*)&A[(size_t)(m0 + r) * K + k0 + kq * 4];
            As[kq * 4 + 0][r] = v.x;
            As[kq * 4 + 1][r] = v.y;
            As[kq * 4 + 2][r] = v.z;
            As[kq * 4 + 3][r] = v.w;
        }
        // Load B tile (BK x BN) as float4 along N
        #pragma unroll
        for (int f = tid; f < BK * BN / 4; f += THREADS) {
            int kr = f / (BN / 4);
            int nq = f % (BN / 4);
            *(float4*)&Bs[kr][nq * 4] =
                *(const float4*)&B[(size_t)(k0 + kr) * N + n0 + nq * 4];
        }
        __syncthreads();

        #pragma unroll
        for (int kk = 0; kk < BK; kk++) {
            float a[TM], b[TN];
            #pragma unroll
            for (int i = 0; i < TM; i += 4)
                *(float4*)&a[i] = *(const float4*)&As[kk][ty * TM + i];
            #pragma unroll
            for (int j = 0; j < TN; j += 4)
                *(float4*)&b[j] = *(const float4*)&Bs[kk][tx * TN + j];
            #pragma unroll
            for (int i = 0; i < TM; i++)
                #pragma unroll
                for (int j = 0; j < TN; j++)
                    acc[i][j] = fmaf(a[i], b[j], acc[i][j]);
        }
        __syncthreads();
    }

    // Epilogue: bias (+ReLU), vectorized stores (TN == 4)
    float4 bv = *(const float4*)&bias[n0 + tx * TN];
    #pragma unroll
    for (int i = 0; i < TM; i++) {
        float4 r;
        r.x = acc[i][0] + bv.x;
        r.y = acc[i][1] + bv.y;
        r.z = acc[i][2] + bv.z;
        r.w = acc[i][3] + bv.w;
        if (RELU) {
            r.x = fmaxf(r.x, 0.0f);
            r.y = fmaxf(r.y, 0.0f);
            r.z = fmaxf(r.z, 0.0f);
            r.w = fmaxf(r.w, 0.0f);
        }
        *(float4*)&C[(size_t)(m0 + ty * TM + i) * N + n0 + tx * TN] = r;
    }
}

// ---------------------------------------------------------------------------
// VQ kernel: per (row-tile of 128, group g)
//   scores = Z(128x32) @ C^T(32x1024)  chunked by 128 codewords,
//   dist = zn - 2*cross + cn,  per-row argmin (tie -> lowest index),
//   gather codeword -> z_q, idx (as float), per-block sum of (z_q - z)^2.
// ---------------------------------------------------------------------------
__global__ __launch_bounds__(256) void vq_kernel(
    const float* __restrict__ ze,        // [NROWS, 256]
    const float* __restrict__ cb,        // [G, 1024, 32]
    float* __restrict__ zq,              // [NROWS, 256]
    float* __restrict__ idxf,            // [NROWS, 8] (float-cast indices)
    float* __restrict__ losspart)        // [gridDim.y * gridDim.x]
{
    __shared__ float Zs[32][136];        // z transposed [d][row]
    __shared__ float Cs[32][136];        // codebook chunk transposed [d][cw]
    __shared__ float CNs[128];           // codeword norms of current chunk
    __shared__ float zn[128];            // row norms
    __shared__ float lsum[128];

    const int tid  = threadIdx.x;
    const int g    = blockIdx.y;
    const int row0 = blockIdx.x * 128;

    const float* zbase = ze + (size_t)row0 * LATENT + g * GD;
    const float* cgb   = cb + (size_t)g * KCB * GD;

    // Load Z tile (128 rows x 32 dims), transpose into smem
    #pragma unroll
    for (int f = tid; f < 1024; f += 256) {
        int r  = f >> 3;
        int dq = f & 7;
        float4 v = *(const float4*)&zbase[(size_t)r * LATENT + dq * 4];
        Zs[dq * 4 + 0][r] = v.x;
        Zs[dq * 4 + 1][r] = v.y;
        Zs[dq * 4 + 2][r] = v.z;
        Zs[dq * 4 + 3][r] = v.w;
    }
    __syncthreads();

    if (tid < 128) {
        float s = 0.0f;
        #pragma unroll
        for (int d = 0; d < 32; d++) { float z = Zs[d][tid]; s = fmaf(z, z, s); }
        zn[tid] = s;
    }
    __syncthreads();

    const int ty = tid >> 4;   // 0..15 -> rows ty*8..ty*8+7
    const int tx = tid & 15;   // 0..15 -> codewords tx*8..tx*8+7 (within chunk)

    float znr[8];
    #pragma unroll
    for (int i = 0; i < 8; i++) znr[i] = zn[ty * 8 + i];

    float best[8];
    int   bidx[8];
    #pragma unroll
    for (int i = 0; i < 8; i++) { best[i] = FLT_MAX; bidx[i] = 0; }

    for (int ch = 0; ch < 8; ch++) {
        __syncthreads();   // previous chunk's readers done before overwrite
        // Load codebook chunk (128 cw x 32 d), transposed
        #pragma unroll
        for (int f = tid; f < 1024; f += 256) {
            int k  = f >> 3;
            int dq = f & 7;
            float4 v = *(const float4*)&cgb[(size_t)(ch * 128 + k) * GD + dq * 4];
            Cs[dq * 4 + 0][k] = v.x;
            Cs[dq * 4 + 1][k] = v.y;
            Cs[dq * 4 + 2][k] = v.z;
            Cs[dq * 4 + 3][k] = v.w;
        }
        __syncthreads();

        if (tid < 128) {
            float s = 0.0f;
            #pragma unroll
            for (int d = 0; d < 32; d++) { float c = Cs[d][tid]; s = fmaf(c, c, s); }
            CNs[tid] = s;
        }

        float acc[8][8];
        #pragma unroll
        for (int i = 0; i < 8; i++)
            #pragma unroll
            for (int j = 0; j < 8; j++) acc[i][j] = 0.0f;

        #pragma unroll
        for (int d = 0; d < 32; d++) {
            float a[8], b[8];
            *(float4*)&a[0] = *(const float4*)&Zs[d][ty * 8];
            *(float4*)&a[4] = *(const float4*)&Zs[d][ty * 8 + 4];
            *(float4*)&b[0] = *(const float4*)&Cs[d][tx * 8];
            *(float4*)&b[4] = *(const float4*)&Cs[d][tx * 8 + 4];
            #pragma unroll
            for (int i = 0; i < 8; i++)
                #pragma unroll
                for (int j = 0; j < 8; j++)
                    acc[i][j] = fmaf(a[i], b[j], acc[i][j]);
        }
        __syncthreads();   // CNs definitely written

        #pragma unroll
        for (int j = 0; j < 8; j++) {
            float cnv  = CNs[tx * 8 + j];
            int   kidx = ch * 128 + tx * 8 + j;
            #pragma unroll
            for (int i = 0; i < 8; i++) {
                float dist = znr[i] + fmaf(-2.0f, acc[i][j], cnv);
                if (dist < best[i]) { best[i] = dist; bidx[i] = kidx; }
            }
        }
    }
    __syncthreads();

    // Cross-thread argmin reduction (reuse Cs storage)
    float* redV = &Cs[0][0];                 // 2048 floats
    int*   redI = (int*)(&Cs[0][0] + 2048);  // 2048 ints
    #pragma unroll
    for (int i = 0; i < 8; i++) {
        redV[(ty * 8 + i) * 16 + tx] = best[i];
        redI[(ty * 8 + i) * 16 + tx] = bidx[i];
    }
    __syncthreads();

    if (tid < 128) {
        int   r  = tid;
        float bv = redV[r * 16];
        int   bi = redI[r * 16];
        #pragma unroll
        for (int t = 1; t < 16; t++) {
            float v = redV[r * 16 + t];
            int   i2 = redI[r * 16 + t];
            if (v < bv || (v == bv && i2 < bi)) { bv = v; bi = i2; }
        }
        int grow = row0 + r;
        idxf[(size_t)grow * GRP + g] = (float)bi;

        const float* cw  = cgb + (size_t)bi * GD;
        float*       zqo = zq + (size_t)grow * LATENT + g * GD;
        float diff2 = 0.0f;
        #pragma unroll
        for (int dq = 0; dq < 8; dq++) {
            float4 c4 = *(const float4*)&cw[dq * 4];
            float z0 = Zs[dq * 4 + 0][r];
            float z1 = Zs[dq * 4 + 1][r];
            float z2 = Zs[dq * 4 + 2][r];
            float z3 = Zs[dq * 4 + 3][r];
            float d0 = c4.x - z0, d1 = c4.y - z1, d2 = c4.z - z2, d3 = c4.w - z3;
            diff2 = fmaf(d0, d0, diff2);
            diff2 = fmaf(d1, d1, diff2);
            diff2 = fmaf(d2, d2, diff2);
            diff2 = fmaf(d3, d3, diff2);
            *(float4*)&zqo[dq * 4] = c4;
        }
        lsum[r] = diff2;
    }
    __syncthreads();

    if (tid == 0) {
        float s = 0.0f;
        for (int r = 0; r < 128; r++) s += lsum[r];
        losspart[blockIdx.y * gridDim.x + blockIdx.x] = s;
    }
}

// ---------------------------------------------------------------------------
// Deterministic loss reduction: vq_loss = total_sq / 1,024,000
//   (= 0.25 * (codebook_loss + commit_loss), both equal in forward values)
// ---------------------------------------------------------------------------
__global__ void loss_reduce(float* __restrict__ out)
{
    __shared__ float s[256];
    int tid = threadIdx.x;
    float v = 0.0f;
    for (int i = tid; i < 1000; i += 256) v += g_loss_part[i];
    s[tid] = v;
    __syncthreads();
    for (int off = 128; off > 0; off >>= 1) {
        if (tid < off) s[tid] += s[tid + off];
        __syncthreads();
    }
    if (tid == 0) out[0] = s[0] * (1.0f / 1024000.0f);
}

// ---------------------------------------------------------------------------
// Launch
// ---------------------------------------------------------------------------
extern "C" void kernel_launch(void* const* d_in, const int* in_sizes, int n_in,
                              void* d_out, int out_size)
{
    const float* bands = (const float*)d_in[0];
    const float* ew1   = (const float*)d_in[1];
    const float* eb1   = (const float*)d_in[2];
    const float* ew2   = (const float*)d_in[3];
    const float* eb2   = (const float*)d_in[4];
    const float* cb    = (const float*)d_in[5];
    const float* dw1   = (const float*)d_in[6];
    const float* db1   = (const float*)d_in[7];
    const float* dw2   = (const float*)d_in[8];
    const float* db2   = (const float*)d_in[9];

    float* out  = (float*)d_out;
    float* bhat = out;                       // 16000*64   = 1,024,000
    float* ze   = bhat + 1024000;            // 16000*256  = 4,096,000
    float* zq   = ze   + 4096000;            // 16000*256  = 4,096,000
    float* idxf = zq   + 4096000;            // 16000*8    =   128,000
    float* loss = idxf + 128000;             // scalar

    float* hid;
    cudaGetSymbolAddress((void**)&hid, g_hidden);
    float* lpart;
    cudaGetSymbolAddress((void**)&lpart, g_loss_part);

    // Encoder
    sgemm_bias<128, 64, 16, 8, 4, true ><<<dim3(HIDDEN / 64, NROWS / 128), 256>>>(
        bands, ew1, eb1, hid, NROWS, HIDDEN, NBANDS);
    sgemm_bias<128, 64, 16, 8, 4, false><<<dim3(LATENT / 64, NROWS / 128), 256>>>(
        hid, ew2, eb2, ze, NROWS, LATENT, HIDDEN);

    // Vector quantization
    vq_kernel<<<dim3(NROWS / 128, GRP), 256>>>(ze, cb, zq, idxf, lpart);
    loss_reduce<<<1, 256>>>(loss);

    // Decoder
    sgemm_bias<128, 64, 16, 8, 4, true ><<<dim3(HIDDEN / 64, NROWS / 128), 256>>>(
        zq, dw1, db1, hid, NROWS, HIDDEN, LATENT);
    sgemm_bias<128, 64, 16, 8, 4, false><<<dim3(NBANDS / 64, NROWS / 128), 256>>>(
        hid, dw2, db2, bhat, NROWS, NBANDS, HIDDEN);
}

// round 2
// speedup vs baseline: 1.0341x; 1.0341x over previous
#include <cuda_runtime.h>
#include <cfloat>

#define NROWS   16000
#define NBANDS  64
#define HIDDEN  512
#define LATENT  256
#define GRP     8
#define GD      32
#define KCB     1024

__device__ float g_hidden[NROWS * HIDDEN];
__device__ float g_loss_part[1024];
__device__ unsigned int g_cnt = 0;

// ---------------------------------------------------------------------------
// Double-buffered SGEMM, fused bias (+ReLU). C[M,N] = act(A[M,K]@B[K,N]+bias)
// 256 threads, TMxTN micro-tile, one __syncthreads per K-tile.
// ---------------------------------------------------------------------------
template<int BM, int BN, int BK, int TM, int TN, bool RELU>
__global__ __launch_bounds__((BM/TM)*(BN/TN), 2) void sgemm_bias(
    const float* __restrict__ A, const float* __restrict__ B,
    const float* __restrict__ bias, float* __restrict__ C,
    int M, int N, int K)
{
    constexpr int THREADS = (BM / TM) * (BN / TN);
    constexpr int A_LD = BM * BK / 4 / THREADS;   // float4 per thread (A tile)
    constexpr int B_LD = BK * BN / 4 / THREADS;   // float4 per thread (B tile)

    __shared__ float As[2][BK][BM + 4];
    __shared__ float Bs[2][BK][BN + 4];

    const int tid = threadIdx.x;
    const int tx  = tid % (BN / TN);
    const int ty  = tid / (BN / TN);
    const int m0  = blockIdx.y * BM;
    const int n0  = blockIdx.x * BN;

    float acc[TM][TN];
    #pragma unroll
    for (int i = 0; i < TM; i++)
        #pragma unroll
        for (int j = 0; j < TN; j++) acc[i][j] = 0.0f;

    float4 ra[A_LD], rb[B_LD];

    auto ldgA = [&](int k0) {
        #pragma unroll
        for (int u = 0; u < A_LD; u++) {
            int f = tid + u * THREADS;
            int r = f / (BK / 4), kq = f % (BK / 4);
            ra[u] = *(const float4*)&A[(size_t)(m0 + r) * K + k0 + kq * 4];
        }
    };
    auto ldgB = [&](int k0) {
        #pragma unroll
        for (int u = 0; u < B_LD; u++) {
            int f = tid + u * THREADS;
            int kr = f / (BN / 4), nq = f % (BN / 4);
            rb[u] = *(const float4*)&B[(size_t)(k0 + kr) * N + n0 + nq * 4];
        }
    };
    auto stsA = [&](int s) {
        #pragma unroll
        for (int u = 0; u < A_LD; u++) {
            int f = tid + u * THREADS;
            int r = f / (BK / 4), kq = f % (BK / 4);
            As[s][kq * 4 + 0][r] = ra[u].x;
            As[s][kq * 4 + 1][r] = ra[u].y;
            As[s][kq * 4 + 2][r] = ra[u].z;
            As[s][kq * 4 + 3][r] = ra[u].w;
        }
    };
    auto stsB = [&](int s) {
        #pragma unroll
        for (int u = 0; u < B_LD; u++) {
            int f = tid + u * THREADS;
            int kr = f / (BN / 4), nq = f % (BN / 4);
            *(float4*)&Bs[s][kr][nq * 4] = rb[u];
        }
    };
    auto compute = [&](int s) {
        #pragma unroll
        for (int kk = 0; kk < BK; kk++) {
            float a[TM], b[TN];
            #pragma unroll
            for (int i = 0; i < TM; i += 4)
                *(float4*)&a[i] = *(const float4*)&As[s][kk][ty * TM + i];
            #pragma unroll
            for (int j = 0; j < TN; j += 4)
                *(float4*)&b[j] = *(const float4*)&Bs[s][kk][tx * TN + j];
            #pragma unroll
            for (int i = 0; i < TM; i++)
                #pragma unroll
                for (int j = 0; j < TN; j++)
                    acc[i][j] = fmaf(a[i], b[j], acc[i][j]);
        }
    };

    ldgA(0); ldgB(0);
    stsA(0); stsB(0);
    __syncthreads();

    int buf = 0;
    for (int k0 = BK; k0 < K; k0 += BK) {
        ldgA(k0); ldgB(k0);          // prefetch next tile into registers
        compute(buf);                 // compute current tile
        stsA(buf ^ 1); stsB(buf ^ 1); // stage next tile
        __syncthreads();
        buf ^= 1;
    }
    compute(buf);

    // Epilogue: bias (+ReLU), float4 stores
    #pragma unroll
    for (int j = 0; j < TN; j += 4) {
        float4 bv = *(const float4*)&bias[n0 + tx * TN + j];
        #pragma unroll
        for (int i = 0; i < TM; i++) {
            float4 r;
            r.x = acc[i][j + 0] + bv.x;
            r.y = acc[i][j + 1] + bv.y;
            r.z = acc[i][j + 2] + bv.z;
            r.w = acc[i][j + 3] + bv.w;
            if (RELU) {
                r.x = fmaxf(r.x, 0.0f); r.y = fmaxf(r.y, 0.0f);
                r.z = fmaxf(r.z, 0.0f); r.w = fmaxf(r.w, 0.0f);
            }
            *(float4*)&C[(size_t)(m0 + ty * TM + i) * N + n0 + tx * TN + j] = r;
        }
    }
}

// ---------------------------------------------------------------------------
// VQ kernel: block = (128 rows, group g). Double-buffered 128-codeword chunks,
// ONE __syncthreads per chunk. dist = zn - 2*cross + cn, argmin (low idx wins),
// gather codeword -> z_q, idx; per-block loss partial; last block reduces loss.
// Dynamic smem layout (floats):
//   Zs  [32][136]        4352
//   Cs  [2][32][136]     8704   (reused as argmin scratch at the end)
//   CN  [2][128]          256
//   zn  [128]             128
//   lsum[128]             128
// ---------------------------------------------------------------------------
#define ZS_W   136
#define VQ_SMEM_FLOATS (4352 + 8704 + 256 + 128 + 128)

__global__ __launch_bounds__(256, 2) void vq_kernel(
    const float* __restrict__ ze,
    const float* __restrict__ cb,
    float* __restrict__ zq,
    float* __restrict__ idxf,
    float* __restrict__ losspart,
    float* __restrict__ lossout)
{
    extern __shared__ float sm[];
    float (*Zs)[ZS_W] = (float(*)[ZS_W])sm;
    float (*Cs)[32][ZS_W] = (float(*)[32][ZS_W])(sm + 32 * ZS_W);
    float* CN   = sm + 3 * 32 * ZS_W;      // [2][128]
    float* zn   = CN + 256;
    float* lsum = zn + 128;

    const int tid  = threadIdx.x;
    const int g    = blockIdx.y;
    const int row0 = blockIdx.x * 128;

    const float* zbase = ze + (size_t)row0 * LATENT + g * GD;
    const float* cgb   = cb + (size_t)g * KCB * GD;

    const int ty = tid >> 4;   // 0..15 -> rows ty*8..+7
    const int tx = tid & 15;   // 0..15 -> codewords tx*8..+7 in chunk

    float4 rc[4];
    auto ldgC = [&](int ch) {
        #pragma unroll
        for (int u = 0; u < 4; u++) {
            int f = tid + u * 256;
            int k = f >> 3, dq = f & 7;
            rc[u] = *(const float4*)&cgb[(size_t)(ch * 128 + k) * GD + dq * 4];
        }
    };
    auto stsC = [&](int s) {
        #pragma unroll
        for (int u = 0; u < 4; u++) {
            int f = tid + u * 256;
            int k = f >> 3, dq = f & 7;
            Cs[s][dq * 4 + 0][k] = rc[u].x;
            Cs[s][dq * 4 + 1][k] = rc[u].y;
            Cs[s][dq * 4 + 2][k] = rc[u].z;
            Cs[s][dq * 4 + 3][k] = rc[u].w;
        }
    };

    // Prologue: Z tile -> smem (transposed), chunk0 -> smem, chunk1 -> regs
    ldgC(0);
    #pragma unroll
    for (int f = tid; f < 1024; f += 256) {
        int r = f >> 3, dq = f & 7;
        float4 v = *(const float4*)&zbase[(size_t)r * LATENT + dq * 4];
        Zs[dq * 4 + 0][r] = v.x;
        Zs[dq * 4 + 1][r] = v.y;
        Zs[dq * 4 + 2][r] = v.z;
        Zs[dq * 4 + 3][r] = v.w;
    }
    stsC(0);
    ldgC(1);
    __syncthreads();   // Zs + Cs[0] ready

    float best[8];
    int   bidx[8];
    #pragma unroll
    for (int i = 0; i < 8; i++) { best[i] = FLT_MAX; bidx[i] = 0; }

    for (int ch = 0; ch < 8; ch++) {
        const int cur = ch & 1;

        if (ch + 1 < 8) stsC(cur ^ 1);    // stage next chunk (buffer idle)
        if (ch + 2 < 8) ldgC(ch + 2);     // prefetch chunk after

        // norms for this chunk (+ row norms on first chunk)
        if (tid < 128) {
            if (ch == 0) {
                float s = 0.0f;
                #pragma unroll
                for (int d = 0; d < 32; d++) { float z = Zs[d][tid]; s = fmaf(z, z, s); }
                zn[tid] = s;
            }
            float s = 0.0f;
            #pragma unroll
            for (int d = 0; d < 32; d++) { float c = Cs[cur][d][tid]; s = fmaf(c, c, s); }
            CN[cur * 128 + tid] = s;
        }

        float acc[8][8];
        #pragma unroll
        for (int i = 0; i < 8; i++)
            #pragma unroll
            for (int j = 0; j < 8; j++) acc[i][j] = 0.0f;

        #pragma unroll
        for (int d = 0; d < 32; d++) {
            float a[8], b[8];
            *(float4*)&a[0] = *(const float4*)&Zs[d][ty * 8];
            *(float4*)&a[4] = *(const float4*)&Zs[d][ty * 8 + 4];
            *(float4*)&b[0] = *(const float4*)&Cs[cur][d][tx * 8];
            *(float4*)&b[4] = *(const float4*)&Cs[cur][d][tx * 8 + 4];
            #pragma unroll
            for (int i = 0; i < 8; i++)
                #pragma unroll
                for (int j = 0; j < 8; j++)
                    acc[i][j] = fmaf(a[i], b[j], acc[i][j]);
        }
        __syncthreads();   // CN[cur]+zn ready; Cs[cur^1] stored; Cs[cur] free next iter

        float znr[8];
        #pragma unroll
        for (int i = 0; i < 8; i++) znr[i] = zn[ty * 8 + i];
        #pragma unroll
        for (int j = 0; j < 8; j++) {
            float cnv  = CN[cur * 128 + tx * 8 + j];
            int   kidx = ch * 128 + tx * 8 + j;
            #pragma unroll
            for (int i = 0; i < 8; i++) {
                float dist = znr[i] + fmaf(-2.0f, acc[i][j], cnv);
                if (dist < best[i]) { best[i] = dist; bidx[i] = kidx; }
            }
        }
    }
    __syncthreads();

    // Cross-thread argmin reduction (reuse Cs storage)
    float* redV = &Cs[0][0][0];
    int*   redI = (int*)(&Cs[0][0][0] + 2048);
    #pragma unroll
    for (int i = 0; i < 8; i++) {
        redV[(ty * 8 + i) * 16 + tx] = best[i];
        redI[(ty * 8 + i) * 16 + tx] = bidx[i];
    }
    __syncthreads();

    if (tid < 128) {
        int   r  = tid;
        float bv = redV[r * 16];
        int   bi = redI[r * 16];
        #pragma unroll
        for (int t = 1; t < 16; t++) {
            float v  = redV[r * 16 + t];
            int   i2 = redI[r * 16 + t];
            if (v < bv || (v == bv && i2 < bi)) { bv = v; bi = i2; }
        }
        int grow = row0 + r;
        idxf[(size_t)grow * GRP + g] = (float)bi;

        const float* cw  = cgb + (size_t)bi * GD;
        float*       zqo = zq + (size_t)grow * LATENT + g * GD;
        float diff2 = 0.0f;
        #pragma unroll
        for (int dq = 0; dq < 8; dq++) {
            float4 c4 = *(const float4*)&cw[dq * 4];
            float d0 = c4.x - Zs[dq * 4 + 0][r];
            float d1 = c4.y - Zs[dq * 4 + 1][r];
            float d2 = c4.z - Zs[dq * 4 + 2][r];
            float d3 = c4.w - Zs[dq * 4 + 3][r];
            diff2 = fmaf(d0, d0, diff2);
            diff2 = fmaf(d1, d1, diff2);
            diff2 = fmaf(d2, d2, diff2);
            diff2 = fmaf(d3, d3, diff2);
            *(float4*)&zqo[dq * 4] = c4;
        }
        lsum[r] = diff2;
    }
    __syncthreads();

    __shared__ bool is_last;
    if (tid == 0) {
        float s = 0.0f;
        for (int r = 0; r < 128; r++) s += lsum[r];
        losspart[blockIdx.y * gridDim.x + blockIdx.x] = s;
        __threadfence();
        unsigned int t = atomicAdd(&g_cnt, 1u);
        is_last = (t == (unsigned int)(gridDim.x * gridDim.y - 1));
    }
    __syncthreads();

    if (is_last) {
        // deterministic final reduction by the last-finishing block
        int npart = gridDim.x * gridDim.y;
        float v = 0.0f;
        for (int i = tid; i < npart; i += 256) v += losspart[i];
        lsum[tid & 127] = 0.0f;   // reuse; need 256 slots -> use redV
        redV[tid] = v;
        __syncthreads();
        for (int off = 128; off > 0; off >>= 1) {
            if (tid < off) redV[tid] += redV[tid + off];
            __syncthreads();
        }
        if (tid == 0) {
            lossout[0] = redV[0] * (1.0f / 1024000.0f);
            g_cnt = 0;   // reset for next graph replay
        }
    }
}

// ---------------------------------------------------------------------------
// Launch
// ---------------------------------------------------------------------------
extern "C" void kernel_launch(void* const* d_in, const int* in_sizes, int n_in,
                              void* d_out, int out_size)
{
    const float* bands = (const float*)d_in[0];
    const float* ew1   = (const float*)d_in[1];
    const float* eb1   = (const float*)d_in[2];
    const float* ew2   = (const float*)d_in[3];
    const float* eb2   = (const float*)d_in[4];
    const float* cb    = (const float*)d_in[5];
    const float* dw1   = (const float*)d_in[6];
    const float* db1   = (const float*)d_in[7];
    const float* dw2   = (const float*)d_in[8];
    const float* db2   = (const float*)d_in[9];

    float* out  = (float*)d_out;
    float* bhat = out;                       // 16000*64
    float* ze   = bhat + 1024000;            // 16000*256
    float* zq   = ze   + 4096000;            // 16000*256
    float* idxf = zq   + 4096000;            // 16000*8
    float* loss = idxf + 128000;             // scalar

    float* hid;
    cudaGetSymbolAddress((void**)&hid, g_hidden);
    float* lpart;
    cudaGetSymbolAddress((void**)&lpart, g_loss_part);

    static bool attr_set = false;
    if (!attr_set) {
        cudaFuncSetAttribute(vq_kernel, cudaFuncAttributeMaxDynamicSharedMemorySize,
                             VQ_SMEM_FLOATS * 4);
        attr_set = true;
    }

    // Encoder
    sgemm_bias<128, 128, 16, 8, 8, true ><<<dim3(HIDDEN / 128, NROWS / 128), 256>>>(
        bands, ew1, eb1, hid, NROWS, HIDDEN, NBANDS);
    sgemm_bias<128, 128, 16, 8, 8, false><<<dim3(LATENT / 128, NROWS / 128), 256>>>(
        hid, ew2, eb2, ze, NROWS, LATENT, HIDDEN);

    // Vector quantization (+ fused deterministic loss reduction)
    vq_kernel<<<dim3(NROWS / 128, GRP), 256, VQ_SMEM_FLOATS * 4>>>(
        ze, cb, zq, idxf, lpart, loss);

    // Decoder
    sgemm_bias<128, 128, 16, 8, 8, true ><<<dim3(HIDDEN / 128, NROWS / 128), 256>>>(
        zq, dw1, db1, hid, NROWS, HIDDEN, LATENT);
    sgemm_bias<128, 64, 16, 8, 4, false><<<dim3(NBANDS / 64, NROWS / 128), 256>>>(
        hid, dw2, db2, bhat, NROWS, NBANDS, HIDDEN);
}

// round 3
// speedup vs baseline: 1.0647x; 1.0297x over previous
#include <cuda_runtime.h>
#include <cfloat>

#define NROWS   16000
#define NBANDS  64
#define HIDDEN  512
#define LATENT  256
#define GRP     8
#define GD      32
#define KCB     1024

__device__ float g_hidden[NROWS * HIDDEN];
__device__ float g_loss_part[1024];
__device__ unsigned int g_cnt = 0;

typedef unsigned long long u64;

// Packed fp32x2 FMA: d = a*b + d  (elementwise on two packed floats; per-lane
// rounding identical to scalar fma.rn.f32)
__device__ __forceinline__ void ffma2(u64& d, u64 a, u64 b) {
    asm("fma.rn.f32x2 %0, %1, %2, %0;" : "+l"(d) : "l"(a), "l"(b));
}
__device__ __forceinline__ u64 dup2(float x) {
    u64 r;
    asm("mov.b64 %0, {%1, %1};" : "=l"(r) : "f"(x));
    return r;
}
__device__ __forceinline__ void unpack2(u64 v, float& lo, float& hi) {
    asm("mov.b64 {%0, %1}, %2;" : "=f"(lo), "=f"(hi) : "l"(v));
}

// ---------------------------------------------------------------------------
// Double-buffered SGEMM with packed-f32x2 inner product, fused bias (+ReLU).
// C[M,N] = act(A[M,K] @ B[K,N] + bias). 256 threads, TM x TN micro-tile.
// ---------------------------------------------------------------------------
template<int BM, int BN, int BK, int TM, int TN, bool RELU>
__global__ __launch_bounds__((BM/TM)*(BN/TN), 2) void sgemm_bias(
    const float* __restrict__ A, const float* __restrict__ B,
    const float* __restrict__ bias, float* __restrict__ C,
    int M, int N, int K)
{
    constexpr int THREADS = (BM / TM) * (BN / TN);
    constexpr int A_LD = BM * BK / 4 / THREADS;
    constexpr int B_LD = BK * BN / 4 / THREADS;
    constexpr int TNP = TN / 2;

    __shared__ __align__(16) float As[2][BK][BM + 4];
    __shared__ __align__(16) float Bs[2][BK][BN + 4];

    const int tid = threadIdx.x;
    const int tx  = tid % (BN / TN);
    const int ty  = tid / (BN / TN);
    const int m0  = blockIdx.y * BM;
    const int n0  = blockIdx.x * BN;

    u64 acc[TM][TNP];
    #pragma unroll
    for (int i = 0; i < TM; i++)
        #pragma unroll
        for (int j = 0; j < TNP; j++) acc[i][j] = 0ull;

    float4 ra[A_LD], rb[B_LD];

    auto ldgA = [&](int k0) {
        #pragma unroll
        for (int u = 0; u < A_LD; u++) {
            int f = tid + u * THREADS;
            int r = f / (BK / 4), kq = f % (BK / 4);
            ra[u] = *(const float4*)&A[(size_t)(m0 + r) * K + k0 + kq * 4];
        }
    };
    auto ldgB = [&](int k0) {
        #pragma unroll
        for (int u = 0; u < B_LD; u++) {
            int f = tid + u * THREADS;
            int kr = f / (BN / 4), nq = f % (BN / 4);
            rb[u] = *(const float4*)&B[(size_t)(k0 + kr) * N + n0 + nq * 4];
        }
    };
    auto stsA = [&](int s) {
        #pragma unroll
        for (int u = 0; u < A_LD; u++) {
            int f = tid + u * THREADS;
            int r = f / (BK / 4), kq = f % (BK / 4);
            As[s][kq * 4 + 0][r] = ra[u].x;
            As[s][kq * 4 + 1][r] = ra[u].y;
            As[s][kq * 4 + 2][r] = ra[u].z;
            As[s][kq * 4 + 3][r] = ra[u].w;
        }
    };
    auto stsB = [&](int s) {
        #pragma unroll
        for (int u = 0; u < B_LD; u++) {
            int f = tid + u * THREADS;
            int kr = f / (BN / 4), nq = f % (BN / 4);
            *(float4*)&Bs[s][kr][nq * 4] = rb[u];
        }
    };
    auto compute = [&](int s) {
        #pragma unroll
        for (int kk = 0; kk < BK; kk++) {
            float a[TM];
            #pragma unroll
            for (int i = 0; i < TM; i += 4)
                *(float4*)&a[i] = *(const float4*)&As[s][kk][ty * TM + i];
            u64 b2[TNP];
            #pragma unroll
            for (int j = 0; j < TNP; j += 2) {
                ulonglong2 bb = *(const ulonglong2*)&Bs[s][kk][tx * TN + j * 2];
                b2[j] = bb.x; b2[j + 1] = bb.y;
            }
            u64 a2[TM];
            #pragma unroll
            for (int i = 0; i < TM; i++) a2[i] = dup2(a[i]);
            #pragma unroll
            for (int i = 0; i < TM; i++)
                #pragma unroll
                for (int j = 0; j < TNP; j++)
                    ffma2(acc[i][j], a2[i], b2[j]);
        }
    };

    ldgA(0); ldgB(0);
    stsA(0); stsB(0);
    __syncthreads();

    int buf = 0;
    for (int k0 = BK; k0 < K; k0 += BK) {
        ldgA(k0); ldgB(k0);
        compute(buf);
        stsA(buf ^ 1); stsB(buf ^ 1);
        __syncthreads();
        buf ^= 1;
    }
    compute(buf);

    // Epilogue: unpack, bias (+ReLU), float4 stores
    #pragma unroll
    for (int j = 0; j < TN; j += 4) {
        float4 bv = *(const float4*)&bias[n0 + tx * TN + j];
        #pragma unroll
        for (int i = 0; i < TM; i++) {
            float4 r;
            unpack2(acc[i][j / 2 + 0], r.x, r.y);
            unpack2(acc[i][j / 2 + 1], r.z, r.w);
            r.x += bv.x; r.y += bv.y; r.z += bv.z; r.w += bv.w;
            if (RELU) {
                r.x = fmaxf(r.x, 0.0f); r.y = fmaxf(r.y, 0.0f);
                r.z = fmaxf(r.z, 0.0f); r.w = fmaxf(r.w, 0.0f);
            }
            *(float4*)&C[(size_t)(m0 + ty * TM + i) * N + n0 + tx * TN + j] = r;
        }
    }
}

// ---------------------------------------------------------------------------
// VQ kernel: block = (128 rows, group g). Double-buffered 128-codeword chunks,
// packed-f32x2 cross-product. dist = zn - 2*cross + cn, argmin (low idx wins),
// gather codeword -> z_q, idx; fused deterministic loss reduction.
// ---------------------------------------------------------------------------
#define ZS_W   136
#define VQ_SMEM_FLOATS (4352 + 8704 + 256 + 128 + 128)

__global__ __launch_bounds__(256, 2) void vq_kernel(
    const float* __restrict__ ze,
    const float* __restrict__ cb,
    float* __restrict__ zq,
    float* __restrict__ idxf,
    float* __restrict__ losspart,
    float* __restrict__ lossout)
{
    extern __shared__ __align__(16) float sm[];
    float (*Zs)[ZS_W] = (float(*)[ZS_W])sm;
    float (*Cs)[32][ZS_W] = (float(*)[32][ZS_W])(sm + 32 * ZS_W);
    float* CN   = sm + 3 * 32 * ZS_W;      // [2][128]
    float* zn   = CN + 256;
    float* lsum = zn + 128;

    const int tid  = threadIdx.x;
    const int g    = blockIdx.y;
    const int row0 = blockIdx.x * 128;

    const float* zbase = ze + (size_t)row0 * LATENT + g * GD;
    const float* cgb   = cb + (size_t)g * KCB * GD;

    const int ty = tid >> 4;
    const int tx = tid & 15;

    float4 rc[4];
    auto ldgC = [&](int ch) {
        #pragma unroll
        for (int u = 0; u < 4; u++) {
            int f = tid + u * 256;
            int k = f >> 3, dq = f & 7;
            rc[u] = *(const float4*)&cgb[(size_t)(ch * 128 + k) * GD + dq * 4];
        }
    };
    auto stsC = [&](int s) {
        #pragma unroll
        for (int u = 0; u < 4; u++) {
            int f = tid + u * 256;
            int k = f >> 3, dq = f & 7;
            Cs[s][dq * 4 + 0][k] = rc[u].x;
            Cs[s][dq * 4 + 1][k] = rc[u].y;
            Cs[s][dq * 4 + 2][k] = rc[u].z;
            Cs[s][dq * 4 + 3][k] = rc[u].w;
        }
    };

    ldgC(0);
    #pragma unroll
    for (int f = tid; f < 1024; f += 256) {
        int r = f >> 3, dq = f & 7;
        float4 v = *(const float4*)&zbase[(size_t)r * LATENT + dq * 4];
        Zs[dq * 4 + 0][r] = v.x;
        Zs[dq * 4 + 1][r] = v.y;
        Zs[dq * 4 + 2][r] = v.z;
        Zs[dq * 4 + 3][r] = v.w;
    }
    stsC(0);
    ldgC(1);
    __syncthreads();

    float best[8];
    int   bidx[8];
    #pragma unroll
    for (int i = 0; i < 8; i++) { best[i] = FLT_MAX; bidx[i] = 0; }

    for (int ch = 0; ch < 8; ch++) {
        const int cur = ch & 1;

        if (ch + 1 < 8) stsC(cur ^ 1);
        if (ch + 2 < 8) ldgC(ch + 2);

        if (tid < 128) {
            if (ch == 0) {
                float s = 0.0f;
                #pragma unroll
                for (int d = 0; d < 32; d++) { float z = Zs[d][tid]; s = fmaf(z, z, s); }
                zn[tid] = s;
            }
            float s = 0.0f;
            #pragma unroll
            for (int d = 0; d < 32; d++) { float c = Cs[cur][d][tid]; s = fmaf(c, c, s); }
            CN[cur * 128 + tid] = s;
        }

        u64 acc[8][4];
        #pragma unroll
        for (int i = 0; i < 8; i++)
            #pragma unroll
            for (int j = 0; j < 4; j++) acc[i][j] = 0ull;

        #pragma unroll
        for (int d = 0; d < 32; d++) {
            float a[8];
            *(float4*)&a[0] = *(const float4*)&Zs[d][ty * 8];
            *(float4*)&a[4] = *(const float4*)&Zs[d][ty * 8 + 4];
            ulonglong2 bb0 = *(const ulonglong2*)&Cs[cur][d][tx * 8];
            ulonglong2 bb1 = *(const ulonglong2*)&Cs[cur][d][tx * 8 + 4];
            u64 b2[4] = {bb0.x, bb0.y, bb1.x, bb1.y};
            u64 a2[8];
            #pragma unroll
            for (int i = 0; i < 8; i++) a2[i] = dup2(a[i]);
            #pragma unroll
            for (int i = 0; i < 8; i++)
                #pragma unroll
                for (int j = 0; j < 4; j++)
                    ffma2(acc[i][j], a2[i], b2[j]);
        }
        __syncthreads();

        float znr[8];
        #pragma unroll
        for (int i = 0; i < 8; i++) znr[i] = zn[ty * 8 + i];
        #pragma unroll
        for (int jp = 0; jp < 4; jp++) {
            float cn0 = CN[cur * 128 + tx * 8 + jp * 2];
            float cn1 = CN[cur * 128 + tx * 8 + jp * 2 + 1];
            int   k0  = ch * 128 + tx * 8 + jp * 2;
            #pragma unroll
            for (int i = 0; i < 8; i++) {
                float c0, c1;
                unpack2(acc[i][jp], c0, c1);
                float d0 = znr[i] + fmaf(-2.0f, c0, cn0);
                float d1 = znr[i] + fmaf(-2.0f, c1, cn1);
                if (d0 < best[i]) { best[i] = d0; bidx[i] = k0; }
                if (d1 < best[i]) { best[i] = d1; bidx[i] = k0 + 1; }
            }
        }
    }
    __syncthreads();

    // Cross-thread argmin reduction (reuse Cs storage)
    float* redV = &Cs[0][0][0];
    int*   redI = (int*)(&Cs[0][0][0] + 2048);
    #pragma unroll
    for (int i = 0; i < 8; i++) {
        redV[(ty * 8 + i) * 16 + tx] = best[i];
        redI[(ty * 8 + i) * 16 + tx] = bidx[i];
    }
    __syncthreads();

    if (tid < 128) {
        int   r  = tid;
        float bv = redV[r * 16];
        int   bi = redI[r * 16];
        #pragma unroll
        for (int t = 1; t < 16; t++) {
            float v  = redV[r * 16 + t];
            int   i2 = redI[r * 16 + t];
            if (v < bv || (v == bv && i2 < bi)) { bv = v; bi = i2; }
        }
        int grow = row0 + r;
        idxf[(size_t)grow * GRP + g] = (float)bi;

        const float* cw  = cgb + (size_t)bi * GD;
        float*       zqo = zq + (size_t)grow * LATENT + g * GD;
        float diff2 = 0.0f;
        #pragma unroll
        for (int dq = 0; dq < 8; dq++) {
            float4 c4 = *(const float4*)&cw[dq * 4];
            float d0 = c4.x - Zs[dq * 4 + 0][r];
            float d1 = c4.y - Zs[dq * 4 + 1][r];
            float d2 = c4.z - Zs[dq * 4 + 2][r];
            float d3 = c4.w - Zs[dq * 4 + 3][r];
            diff2 = fmaf(d0, d0, diff2);
            diff2 = fmaf(d1, d1, diff2);
            diff2 = fmaf(d2, d2, diff2);
            diff2 = fmaf(d3, d3, diff2);
            *(float4*)&zqo[dq * 4] = c4;
        }
        lsum[r] = diff2;
    }
    __syncthreads();

    __shared__ bool is_last;
    if (tid == 0) {
        float s = 0.0f;
        for (int r = 0; r < 128; r++) s += lsum[r];
        losspart[blockIdx.y * gridDim.x + blockIdx.x] = s;
        __threadfence();
        unsigned int t = atomicAdd(&g_cnt, 1u);
        is_last = (t == (unsigned int)(gridDim.x * gridDim.y - 1));
    }
    __syncthreads();

    if (is_last) {
        int npart = gridDim.x * gridDim.y;
        float v = 0.0f;
        for (int i = tid; i < npart; i += 256) v += losspart[i];
        redV[tid] = v;
        __syncthreads();
        for (int off = 128; off > 0; off >>= 1) {
            if (tid < off) redV[tid] += redV[tid + off];
            __syncthreads();
        }
        if (tid == 0) {
            lossout[0] = redV[0] * (1.0f / 1024000.0f);
            g_cnt = 0;
        }
    }
}

// ---------------------------------------------------------------------------
extern "C" void kernel_launch(void* const* d_in, const int* in_sizes, int n_in,
                              void* d_out, int out_size)
{
    const float* bands = (const float*)d_in[0];
    const float* ew1   = (const float*)d_in[1];
    const float* eb1   = (const float*)d_in[2];
    const float* ew2   = (const float*)d_in[3];
    const float* eb2   = (const float*)d_in[4];
    const float* cb    = (const float*)d_in[5];
    const float* dw1   = (const float*)d_in[6];
    const float* db1   = (const float*)d_in[7];
    const float* dw2   = (const float*)d_in[8];
    const float* db2   = (const float*)d_in[9];

    float* out  = (float*)d_out;
    float* bhat = out;
    float* ze   = bhat + 1024000;
    float* zq   = ze   + 4096000;
    float* idxf = zq   + 4096000;
    float* loss = idxf + 128000;

    float* hid;
    cudaGetSymbolAddress((void**)&hid, g_hidden);
    float* lpart;
    cudaGetSymbolAddress((void**)&lpart, g_loss_part);

    cudaFuncSetAttribute(vq_kernel, cudaFuncAttributeMaxDynamicSharedMemorySize,
                         VQ_SMEM_FLOATS * 4);

    // Encoder
    sgemm_bias<128, 128, 16, 8, 8, true ><<<dim3(HIDDEN / 128, NROWS / 128), 256>>>(
        bands, ew1, eb1, hid, NROWS, HIDDEN, NBANDS);
    sgemm_bias<128, 128, 16, 8, 8, false><<<dim3(LATENT / 128, NROWS / 128), 256>>>(
        hid, ew2, eb2, ze, NROWS, LATENT, HIDDEN);

    // Vector quantization (+ fused deterministic loss reduction)
    vq_kernel<<<dim3(NROWS / 128, GRP), 256, VQ_SMEM_FLOATS * 4>>>(
        ze, cb, zq, idxf, lpart, loss);

    // Decoder
    sgemm_bias<128, 128, 16, 8, 8, true ><<<dim3(HIDDEN / 128, NROWS / 128), 256>>>(
        zq, dw1, db1, hid, NROWS, HIDDEN, LATENT);
    sgemm_bias<128, 64, 16, 8, 4, false><<<dim3(NBANDS / 64, NROWS / 128), 256>>>(
        hid, dw2, db2, bhat, NROWS, NBANDS, HIDDEN);
}

// round 5
// speedup vs baseline: 1.1525x; 1.0824x over previous
#include <cuda_runtime.h>
#include <cstdint>
#include <cfloat>

#define NROWS   16000
#define NBANDS  64
#define HIDDEN  512
#define LATENT  256
#define GRP     8
#define GD      32
#define KCB     1024

__device__ float g_hidden[NROWS * HIDDEN];
__device__ float g_loss_part[1024];
__device__ unsigned int g_cnt = 0;

typedef unsigned long long u64;

// ===========================================================================
// Helpers
// ===========================================================================
__device__ __forceinline__ uint32_t smem_u32(const void* p) {
    uint32_t a;
    asm("{ .reg .u64 t; cvta.to.shared.u64 t, %1; cvt.u32.u64 %0, t; }" : "=r"(a) : "l"(p));
    return a;
}
__device__ __forceinline__ uint32_t tf32_of(float x) {
    uint32_t r;
    asm("cvt.rna.tf32.f32 %0, %1;" : "=r"(r) : "f"(x));
    return r;
}
__device__ __forceinline__ void cp_async16(uint32_t saddr, const void* g) {
    asm volatile("cp.async.cg.shared.global [%0], [%1], 16;" :: "r"(saddr), "l"(g));
}
#define CP_COMMIT() asm volatile("cp.async.commit_group;" ::: "memory")
#define CP_WAIT0()  asm volatile("cp.async.wait_group 0;" ::: "memory")
#define CP_WAIT1()  asm volatile("cp.async.wait_group 1;" ::: "memory")

// mma.sync m16n8k8 tf32: D(f32) += A(tf32) * B(tf32)
__device__ __forceinline__ void mma_tf32(float* c, const uint32_t* a, uint32_t b0, uint32_t b1) {
    asm volatile(
        "mma.sync.aligned.m16n8k8.row.col.f32.tf32.tf32.f32 "
        "{%0,%1,%2,%3}, {%4,%5,%6,%7}, {%8,%9}, {%0,%1,%2,%3};"
        : "+f"(c[0]), "+f"(c[1]), "+f"(c[2]), "+f"(c[3])
        : "r"(a[0]), "r"(a[1]), "r"(a[2]), "r"(a[3]), "r"(b0), "r"(b1));
}

// ===========================================================================
// Tensor-core GEMM (3xtf32 via mma.sync): C[M,N] = act(A[M,K] @ W[K,N] + bias)
// BM=128, BK=32, 256 threads = 8 warps (4 M x 2 N), warp tile 32 x (BN/2).
// cp.async double-buffered smem. Conflict-free fragment strides.
// ===========================================================================
template<int BN, bool RELU>
__global__ __launch_bounds__(256, 2) void tgemm(
    const float* __restrict__ A, const float* __restrict__ W,
    const float* __restrict__ bias, float* __restrict__ C,
    int M, int N, int K)
{
    constexpr int BM = 128, BK = 32;
    constexpr int ASTR = BK + 4;           // 36: A frag banks (4m+k)%32 distinct
    constexpr int BSTR = BN + 8;           // %32==8: B frag banks (8k+n)%32 distinct
    constexpr int WN  = BN / 2;            // warp N tile
    constexpr int NT  = WN / 8;            // n8 tiles per warp
    constexpr int A_Q = BM * (BK / 4) / 256;          // float4 per thread (A) = 4
    constexpr int B_Q = BK * (BN / 4) / 256;          // float4 per thread (B)

    extern __shared__ float sm[];
    float* AsBuf[2] = { sm, sm + BM * ASTR };
    float* BsBuf[2] = { sm + 2 * BM * ASTR, sm + 2 * BM * ASTR + BK * BSTR };

    const int tid = threadIdx.x;
    const int wid = tid >> 5;
    const int lane = tid & 31;
    const int grp = lane >> 2;     // 0..7
    const int ctg = lane & 3;      // 0..3
    const int wy  = wid & 3;       // M warp index (4)
    const int wx  = wid >> 2;      // N warp index (2)
    const int m0  = blockIdx.y * BM;
    const int n0  = blockIdx.x * BN;

    float acc[2][NT][4];
    #pragma unroll
    for (int mt = 0; mt < 2; mt++)
        #pragma unroll
        for (int nt = 0; nt < NT; nt++)
            #pragma unroll
            for (int q = 0; q < 4; q++) acc[mt][nt][q] = 0.0f;

    auto copy_chunk = [&](int ch, int buf) {
        const int k0 = ch * BK;
        uint32_t as = smem_u32(AsBuf[buf]);
        uint32_t bs = smem_u32(BsBuf[buf]);
        #pragma unroll
        for (int u = 0; u < A_Q; u++) {
            int f = tid + u * 256;           // 1024 slots: 128 rows x 8 quads
            int r = f >> 3, q = f & 7;
            cp_async16(as + (uint32_t)(r * ASTR + q * 4) * 4,
                       &A[(size_t)(m0 + r) * K + k0 + q * 4]);
        }
        #pragma unroll
        for (int u = 0; u < B_Q; u++) {
            int f = tid + u * 256;           // BK rows x BN/4 quads
            int kr = f / (BN / 4), nq = f % (BN / 4);
            cp_async16(bs + (uint32_t)(kr * BSTR + nq * 4) * 4,
                       &W[(size_t)(k0 + kr) * N + n0 + nq * 4]);
        }
        CP_COMMIT();
    };

    auto compute = [&](int buf) {
        const float* As = AsBuf[buf];
        const float* Bs = BsBuf[buf];
        #pragma unroll
        for (int ks = 0; ks < BK / 8; ks++) {
            const int k8 = ks * 8;
            // A fragments (2 m16 tiles), fp32 -> big/res tf32 in regs
            uint32_t abig[2][4], ares[2][4];
            #pragma unroll
            for (int mt = 0; mt < 2; mt++) {
                const int rb = wy * 32 + mt * 16;
                float af[4];
                af[0] = As[(rb + grp) * ASTR + k8 + ctg];
                af[1] = As[(rb + 8 + grp) * ASTR + k8 + ctg];
                af[2] = As[(rb + grp) * ASTR + k8 + 4 + ctg];
                af[3] = As[(rb + 8 + grp) * ASTR + k8 + 4 + ctg];
                #pragma unroll
                for (int q = 0; q < 4; q++) {
                    abig[mt][q] = tf32_of(af[q]);
                    ares[mt][q] = tf32_of(af[q] - __uint_as_float(abig[mt][q]));
                }
            }
            #pragma unroll
            for (int nt = 0; nt < NT; nt++) {
                const int col = wx * WN + nt * 8 + grp;
                float bf0 = Bs[(k8 + ctg) * BSTR + col];
                float bf1 = Bs[(k8 + 4 + ctg) * BSTR + col];
                uint32_t bb0 = tf32_of(bf0);
                uint32_t bb1 = tf32_of(bf1);
                uint32_t br0 = tf32_of(bf0 - __uint_as_float(bb0));
                uint32_t br1 = tf32_of(bf1 - __uint_as_float(bb1));
                #pragma unroll
                for (int mt = 0; mt < 2; mt++) {
                    mma_tf32(acc[mt][nt], abig[mt], bb0, bb1);
                    mma_tf32(acc[mt][nt], abig[mt], br0, br1);
                    mma_tf32(acc[mt][nt], ares[mt], bb0, bb1);
                }
            }
        }
    };

    const int nch = K / BK;
    copy_chunk(0, 0);
    for (int ch = 0; ch < nch; ch++) {
        const int cur = ch & 1;
        if (ch + 1 < nch) { copy_chunk(ch + 1, cur ^ 1); CP_WAIT1(); }
        else              { CP_WAIT0(); }
        __syncthreads();
        compute(cur);
        __syncthreads();
    }

    // Epilogue: bias (+ReLU), float2 stores
    #pragma unroll
    for (int mt = 0; mt < 2; mt++) {
        const int r0 = m0 + wy * 32 + mt * 16 + grp;
        #pragma unroll
        for (int nt = 0; nt < NT; nt++) {
            const int col = n0 + wx * WN + nt * 8 + 2 * ctg;
            float b0 = bias[col], b1 = bias[col + 1];
            float2 v0, v1;
            v0.x = acc[mt][nt][0] + b0; v0.y = acc[mt][nt][1] + b1;
            v1.x = acc[mt][nt][2] + b0; v1.y = acc[mt][nt][3] + b1;
            if (RELU) {
                v0.x = fmaxf(v0.x, 0.0f); v0.y = fmaxf(v0.y, 0.0f);
                v1.x = fmaxf(v1.x, 0.0f); v1.y = fmaxf(v1.y, 0.0f);
            }
            *(float2*)&C[(size_t)r0 * N + col] = v0;
            *(float2*)&C[(size_t)(r0 + 8) * N + col] = v1;
        }
    }
}

// ===========================================================================
// VQ kernel (unchanged from round 3)
// ===========================================================================
__device__ __forceinline__ void ffma2(u64& d, u64 a, u64 b) {
    asm("fma.rn.f32x2 %0, %1, %2, %0;" : "+l"(d) : "l"(a), "l"(b));
}
__device__ __forceinline__ u64 dup2(float x) {
    u64 r; asm("mov.b64 %0, {%1, %1};" : "=l"(r) : "f"(x)); return r;
}
__device__ __forceinline__ void unpack2(u64 v, float& lo, float& hi) {
    asm("mov.b64 {%0, %1}, %2;" : "=f"(lo), "=f"(hi) : "l"(v));
}

#define ZS_W   136
#define VQ_SMEM_FLOATS (4352 + 8704 + 256 + 128 + 128)

__global__ __launch_bounds__(256, 2) void vq_kernel(
    const float* __restrict__ ze,
    const float* __restrict__ cb,
    float* __restrict__ zq,
    float* __restrict__ idxf,
    float* __restrict__ losspart,
    float* __restrict__ lossout)
{
    extern __shared__ __align__(16) float sm[];
    float (*Zs)[ZS_W] = (float(*)[ZS_W])sm;
    float (*Cs)[32][ZS_W] = (float(*)[32][ZS_W])(sm + 32 * ZS_W);
    float* CN   = sm + 3 * 32 * ZS_W;
    float* zn   = CN + 256;
    float* lsum = zn + 128;

    const int tid  = threadIdx.x;
    const int g    = blockIdx.y;
    const int row0 = blockIdx.x * 128;

    const float* zbase = ze + (size_t)row0 * LATENT + g * GD;
    const float* cgb   = cb + (size_t)g * KCB * GD;

    const int ty = tid >> 4;
    const int tx = tid & 15;

    float4 rc[4];
    auto ldgC = [&](int ch) {
        #pragma unroll
        for (int u = 0; u < 4; u++) {
            int f = tid + u * 256;
            int k = f >> 3, dq = f & 7;
            rc[u] = *(const float4*)&cgb[(size_t)(ch * 128 + k) * GD + dq * 4];
        }
    };
    auto stsC = [&](int s) {
        #pragma unroll
        for (int u = 0; u < 4; u++) {
            int f = tid + u * 256;
            int k = f >> 3, dq = f & 7;
            Cs[s][dq * 4 + 0][k] = rc[u].x;
            Cs[s][dq * 4 + 1][k] = rc[u].y;
            Cs[s][dq * 4 + 2][k] = rc[u].z;
            Cs[s][dq * 4 + 3][k] = rc[u].w;
        }
    };

    ldgC(0);
    #pragma unroll
    for (int f = tid; f < 1024; f += 256) {
        int r = f >> 3, dq = f & 7;
        float4 v = *(const float4*)&zbase[(size_t)r * LATENT + dq * 4];
        Zs[dq * 4 + 0][r] = v.x;
        Zs[dq * 4 + 1][r] = v.y;
        Zs[dq * 4 + 2][r] = v.z;
        Zs[dq * 4 + 3][r] = v.w;
    }
    stsC(0);
    ldgC(1);
    __syncthreads();

    float best[8];
    int   bidx[8];
    #pragma unroll
    for (int i = 0; i < 8; i++) { best[i] = FLT_MAX; bidx[i] = 0; }

    for (int ch = 0; ch < 8; ch++) {
        const int cur = ch & 1;

        if (ch + 1 < 8) stsC(cur ^ 1);
        if (ch + 2 < 8) ldgC(ch + 2);

        if (tid < 128) {
            if (ch == 0) {
                float s = 0.0f;
                #pragma unroll
                for (int d = 0; d < 32; d++) { float z = Zs[d][tid]; s = fmaf(z, z, s); }
                zn[tid] = s;
            }
            float s = 0.0f;
            #pragma unroll
            for (int d = 0; d < 32; d++) { float c = Cs[cur][d][tid]; s = fmaf(c, c, s); }
            CN[cur * 128 + tid] = s;
        }

        u64 acc[8][4];
        #pragma unroll
        for (int i = 0; i < 8; i++)
            #pragma unroll
            for (int j = 0; j < 4; j++) acc[i][j] = 0ull;

        #pragma unroll
        for (int d = 0; d < 32; d++) {
            float a[8];
            *(float4*)&a[0] = *(const float4*)&Zs[d][ty * 8];
            *(float4*)&a[4] = *(const float4*)&Zs[d][ty * 8 + 4];
            ulonglong2 bb0 = *(const ulonglong2*)&Cs[cur][d][tx * 8];
            ulonglong2 bb1 = *(const ulonglong2*)&Cs[cur][d][tx * 8 + 4];
            u64 b2[4] = {bb0.x, bb0.y, bb1.x, bb1.y};
            u64 a2[8];
            #pragma unroll
            for (int i = 0; i < 8; i++) a2[i] = dup2(a[i]);
            #pragma unroll
            for (int i = 0; i < 8; i++)
                #pragma unroll
                for (int j = 0; j < 4; j++)
                    ffma2(acc[i][j], a2[i], b2[j]);
        }
        __syncthreads();

        float znr[8];
        #pragma unroll
        for (int i = 0; i < 8; i++) znr[i] = zn[ty * 8 + i];
        #pragma unroll
        for (int jp = 0; jp < 4; jp++) {
            float cn0 = CN[cur * 128 + tx * 8 + jp * 2];
            float cn1 = CN[cur * 128 + tx * 8 + jp * 2 + 1];
            int   k0  = ch * 128 + tx * 8 + jp * 2;
            #pragma unroll
            for (int i = 0; i < 8; i++) {
                float c0, c1;
                unpack2(acc[i][jp], c0, c1);
                float d0 = znr[i] + fmaf(-2.0f, c0, cn0);
                float d1 = znr[i] + fmaf(-2.0f, c1, cn1);
                if (d0 < best[i]) { best[i] = d0; bidx[i] = k0; }
                if (d1 < best[i]) { best[i] = d1; bidx[i] = k0 + 1; }
            }
        }
    }
    __syncthreads();

    float* redV = &Cs[0][0][0];
    int*   redI = (int*)(&Cs[0][0][0] + 2048);
    #pragma unroll
    for (int i = 0; i < 8; i++) {
        redV[(ty * 8 + i) * 16 + tx] = best[i];
        redI[(ty * 8 + i) * 16 + tx] = bidx[i];
    }
    __syncthreads();

    if (tid < 128) {
        int   r  = tid;
        float bv = redV[r * 16];
        int   bi = redI[r * 16];
        #pragma unroll
        for (int t = 1; t < 16; t++) {
            float v  = redV[r * 16 + t];
            int   i2 = redI[r * 16 + t];
            if (v < bv || (v == bv && i2 < bi)) { bv = v; bi = i2; }
        }
        int grow = row0 + r;
        idxf[(size_t)grow * GRP + g] = (float)bi;

        const float* cw  = cgb + (size_t)bi * GD;
        float*       zqo = zq + (size_t)grow * LATENT + g * GD;
        float diff2 = 0.0f;
        #pragma unroll
        for (int dq = 0; dq < 8; dq++) {
            float4 c4 = *(const float4*)&cw[dq * 4];
            float d0 = c4.x - Zs[dq * 4 + 0][r];
            float d1 = c4.y - Zs[dq * 4 + 1][r];
            float d2 = c4.z - Zs[dq * 4 + 2][r];
            float d3 = c4.w - Zs[dq * 4 + 3][r];
            diff2 = fmaf(d0, d0, diff2);
            diff2 = fmaf(d1, d1, diff2);
            diff2 = fmaf(d2, d2, diff2);
            diff2 = fmaf(d3, d3, diff2);
            *(float4*)&zqo[dq * 4] = c4;
        }
        lsum[r] = diff2;
    }
    __syncthreads();

    __shared__ bool is_last;
    if (tid == 0) {
        float s = 0.0f;
        for (int r = 0; r < 128; r++) s += lsum[r];
        losspart[blockIdx.y * gridDim.x + blockIdx.x] = s;
        __threadfence();
        unsigned int t = atomicAdd(&g_cnt, 1u);
        is_last = (t == (unsigned int)(gridDim.x * gridDim.y - 1));
    }
    __syncthreads();

    if (is_last) {
        int npart = gridDim.x * gridDim.y;
        float v = 0.0f;
        for (int i = tid; i < npart; i += 256) v += losspart[i];
        redV[tid] = v;
        __syncthreads();
        for (int off = 128; off > 0; off >>= 1) {
            if (tid < off) redV[tid] += redV[tid + off];
            __syncthreads();
        }
        if (tid == 0) {
            lossout[0] = redV[0] * (1.0f / 1024000.0f);
            g_cnt = 0;
        }
    }
}

// ===========================================================================
extern "C" void kernel_launch(void* const* d_in, const int* in_sizes, int n_in,
                              void* d_out, int out_size)
{
    const float* bands = (const float*)d_in[0];
    const float* ew1   = (const float*)d_in[1];
    const float* eb1   = (const float*)d_in[2];
    const float* ew2   = (const float*)d_in[3];
    const float* eb2   = (const float*)d_in[4];
    const float* cb    = (const float*)d_in[5];
    const float* dw1   = (const float*)d_in[6];
    const float* db1   = (const float*)d_in[7];
    const float* dw2   = (const float*)d_in[8];
    const float* db2   = (const float*)d_in[9];

    float* out  = (float*)d_out;
    float* bhat = out;
    float* ze   = bhat + 1024000;
    float* zq   = ze   + 4096000;
    float* idxf = zq   + 4096000;
    float* loss = idxf + 128000;

    float* hid;   cudaGetSymbolAddress((void**)&hid,   g_hidden);
    float* lpart; cudaGetSymbolAddress((void**)&lpart, g_loss_part);

    // smem sizes: BN=128: 2*(128*36 + 32*136)*4 = 71680 B; BN=64: 2*(128*36 + 32*72)*4 = 55296 B
    const int SM128 = 2 * (128 * 36 + 32 * 136) * 4;
    const int SM64  = 2 * (128 * 36 + 32 * 72) * 4;
    cudaFuncSetAttribute(tgemm<128, true >, cudaFuncAttributeMaxDynamicSharedMemorySize, SM128);
    cudaFuncSetAttribute(tgemm<128, false>, cudaFuncAttributeMaxDynamicSharedMemorySize, SM128);
    cudaFuncSetAttribute(tgemm<64,  false>, cudaFuncAttributeMaxDynamicSharedMemorySize, SM64);
    cudaFuncSetAttribute(vq_kernel, cudaFuncAttributeMaxDynamicSharedMemorySize, VQ_SMEM_FLOATS * 4);

    // Encoder (HMMA tf32 3x)
    tgemm<128, true ><<<dim3(HIDDEN / 128, NROWS / 128), 256, SM128>>>(
        bands, ew1, eb1, hid, NROWS, HIDDEN, NBANDS);
    tgemm<128, false><<<dim3(LATENT / 128, NROWS / 128), 256, SM128>>>(
        hid, ew2, eb2, ze, NROWS, LATENT, HIDDEN);

    // Vector quantization (+ fused deterministic loss reduction)
    vq_kernel<<<dim3(NROWS / 128, GRP), 256, VQ_SMEM_FLOATS * 4>>>(
        ze, cb, zq, idxf, lpart, loss);

    // Decoder
    tgemm<128, true ><<<dim3(HIDDEN / 128, NROWS / 128), 256, SM128>>>(
        zq, dw1, db1, hid, NROWS, HIDDEN, LATENT);
    tgemm<64,  false><<<dim3(NBANDS / 64, NROWS / 128), 256, SM64>>>(
        hid, dw2, db2, bhat, NROWS, NBANDS, HIDDEN);
}

// round 6
// speedup vs baseline: 1.2460x; 1.0811x over previous
#include <cuda_runtime.h>
#include <cstdint>
#include <cfloat>

#define NROWS   16000
#define NBANDS  64
#define HIDDEN  512
#define LATENT  256
#define GRP     8
#define GD      32
#define KCB     1024

__device__ float g_hidden[NROWS * HIDDEN];
__device__ float g_loss_part[1024];
__device__ unsigned int g_cnt = 0;

// Pre-split (tf32 big/res) weights, [K][N] layout, concatenated:
// e1 64x512 @0 | e2 512x256 @32768 | d1 256x512 @163840 | d2 512x64 @294912
#define WT_TOTAL 327680
__device__ float g_wtb[WT_TOTAL];
__device__ float g_wtr[WT_TOTAL];
// Pre-split codebook [G][K][32] + norms
__device__ float g_cbb[GRP * KCB * GD];
__device__ float g_cbr[GRP * KCB * GD];
__device__ float g_cn2[GRP * KCB];

// ===========================================================================
// Helpers
// ===========================================================================
__device__ __forceinline__ uint32_t smem_u32(const void* p) {
    uint32_t a;
    asm("{ .reg .u64 t; cvta.to.shared.u64 t, %1; cvt.u32.u64 %0, t; }" : "=r"(a) : "l"(p));
    return a;
}
__device__ __forceinline__ uint32_t tf32_of(float x) {
    uint32_t r;
    asm("cvt.rna.tf32.f32 %0, %1;" : "=r"(r) : "f"(x));
    return r;
}
__device__ __forceinline__ void cp_async16(uint32_t saddr, const void* g) {
    asm volatile("cp.async.cg.shared.global [%0], [%1], 16;" :: "r"(saddr), "l"(g));
}
#define CP_COMMIT() asm volatile("cp.async.commit_group;" ::: "memory")
#define CP_WAIT0()  asm volatile("cp.async.wait_group 0;" ::: "memory")
#define CP_WAIT1()  asm volatile("cp.async.wait_group 1;" ::: "memory")

__device__ __forceinline__ void mma_tf32(float* c, const uint32_t* a, uint32_t b0, uint32_t b1) {
    asm volatile(
        "mma.sync.aligned.m16n8k8.row.col.f32.tf32.tf32.f32 "
        "{%0,%1,%2,%3}, {%4,%5,%6,%7}, {%8,%9}, {%0,%1,%2,%3};"
        : "+f"(c[0]), "+f"(c[1]), "+f"(c[2]), "+f"(c[3])
        : "r"(a[0]), "r"(a[1]), "r"(a[2]), "r"(a[3]), "r"(b0), "r"(b1));
}

// ===========================================================================
// Split kernels (run once per launch; tiny)
// ===========================================================================
__global__ void wsplit(const float* __restrict__ w, float* __restrict__ wb,
                       float* __restrict__ wr, int total)
{
    int i = blockIdx.x * 256 + threadIdx.x;
    if (i >= total) return;
    float x = w[i];
    uint32_t b = tf32_of(x);
    wb[i] = __uint_as_float(b);
    wr[i] = __uint_as_float(tf32_of(x - __uint_as_float(b)));
}

__global__ void csplit(const float* __restrict__ cb, float* __restrict__ cbb,
                       float* __restrict__ cbr, float* __restrict__ cn2)
{
    int row = blockIdx.x * 256 + threadIdx.x;   // 8192 codeword rows
    if (row >= GRP * KCB) return;
    const float* src = cb + (size_t)row * GD;
    float s = 0.0f;
    #pragma unroll
    for (int d = 0; d < GD; d++) {
        float x = src[d];
        uint32_t b = tf32_of(x);
        cbb[(size_t)row * GD + d] = __uint_as_float(b);
        cbr[(size_t)row * GD + d] = __uint_as_float(tf32_of(x - __uint_as_float(b)));
        s = fmaf(x, x, s);
    }
    cn2[row] = s;
}

// ===========================================================================
// Tensor-core GEMM (3xtf32), B pre-split: C = act(A[M,K] @ W[K,N] + bias)
// BM=128, BK=32, 8 warps (4M x 2N), warp tile 32 x (BN/2).
// ===========================================================================
template<int BN, bool RELU>
__global__ __launch_bounds__(256, 2) void tgemm(
    const float* __restrict__ A,
    const float* __restrict__ Wb, const float* __restrict__ Wr,
    const float* __restrict__ bias, float* __restrict__ C,
    int M, int N, int K)
{
    constexpr int BM = 128, BK = 32;
    constexpr int ASTR = BK + 4;           // 36
    constexpr int BSTR = BN + 8;
    constexpr int WN  = BN / 2;
    constexpr int NT  = WN / 8;
    constexpr int A_Q = BM * (BK / 4) / 256;
    constexpr int B_Q = BK * (BN / 4) / 256;

    extern __shared__ float sm[];
    float* AsBuf[2] = { sm, sm + BM * ASTR };
    float* BbBuf[2] = { sm + 2 * BM * ASTR, sm + 2 * BM * ASTR + BK * BSTR };
    float* BrBuf[2] = { sm + 2 * BM * ASTR + 2 * BK * BSTR,
                        sm + 2 * BM * ASTR + 3 * BK * BSTR };

    const int tid = threadIdx.x;
    const int wid = tid >> 5;
    const int lane = tid & 31;
    const int grp = lane >> 2;
    const int ctg = lane & 3;
    const int wy  = wid & 3;
    const int wx  = wid >> 2;
    const int m0  = blockIdx.y * BM;
    const int n0  = blockIdx.x * BN;

    float acc[2][NT][4];
    #pragma unroll
    for (int mt = 0; mt < 2; mt++)
        #pragma unroll
        for (int nt = 0; nt < NT; nt++)
            #pragma unroll
            for (int q = 0; q < 4; q++) acc[mt][nt][q] = 0.0f;

    auto copy_chunk = [&](int ch, int buf) {
        const int k0 = ch * BK;
        uint32_t as = smem_u32(AsBuf[buf]);
        uint32_t bb = smem_u32(BbBuf[buf]);
        uint32_t br = smem_u32(BrBuf[buf]);
        #pragma unroll
        for (int u = 0; u < A_Q; u++) {
            int f = tid + u * 256;
            int r = f >> 3, q = f & 7;
            cp_async16(as + (uint32_t)(r * ASTR + q * 4) * 4,
                       &A[(size_t)(m0 + r) * K + k0 + q * 4]);
        }
        #pragma unroll
        for (int u = 0; u < B_Q; u++) {
            int f = tid + u * 256;
            int kr = f / (BN / 4), nq = f % (BN / 4);
            size_t gi = (size_t)(k0 + kr) * N + n0 + nq * 4;
            uint32_t so = (uint32_t)(kr * BSTR + nq * 4) * 4;
            cp_async16(bb + so, &Wb[gi]);
            cp_async16(br + so, &Wr[gi]);
        }
        CP_COMMIT();
    };

    auto compute = [&](int buf) {
        const float* As = AsBuf[buf];
        const float* Bb = BbBuf[buf];
        const float* Br = BrBuf[buf];
        #pragma unroll
        for (int ks = 0; ks < BK / 8; ks++) {
            const int k8 = ks * 8;
            uint32_t abig[2][4], ares[2][4];
            #pragma unroll
            for (int mt = 0; mt < 2; mt++) {
                const int rb = wy * 32 + mt * 16;
                float af[4];
                af[0] = As[(rb + grp) * ASTR + k8 + ctg];
                af[1] = As[(rb + 8 + grp) * ASTR + k8 + ctg];
                af[2] = As[(rb + grp) * ASTR + k8 + 4 + ctg];
                af[3] = As[(rb + 8 + grp) * ASTR + k8 + 4 + ctg];
                #pragma unroll
                for (int q = 0; q < 4; q++) {
                    abig[mt][q] = tf32_of(af[q]);
                    ares[mt][q] = tf32_of(af[q] - __uint_as_float(abig[mt][q]));
                }
            }
            #pragma unroll
            for (int nt = 0; nt < NT; nt++) {
                const int col = wx * WN + nt * 8 + grp;
                uint32_t bb0 = __float_as_uint(Bb[(k8 + ctg) * BSTR + col]);
                uint32_t bb1 = __float_as_uint(Bb[(k8 + 4 + ctg) * BSTR + col]);
                uint32_t br0 = __float_as_uint(Br[(k8 + ctg) * BSTR + col]);
                uint32_t br1 = __float_as_uint(Br[(k8 + 4 + ctg) * BSTR + col]);
                #pragma unroll
                for (int mt = 0; mt < 2; mt++) {
                    mma_tf32(acc[mt][nt], abig[mt], bb0, bb1);
                    mma_tf32(acc[mt][nt], abig[mt], br0, br1);
                    mma_tf32(acc[mt][nt], ares[mt], bb0, bb1);
                }
            }
        }
    };

    const int nch = K / BK;
    copy_chunk(0, 0);
    for (int ch = 0; ch < nch; ch++) {
        const int cur = ch & 1;
        if (ch + 1 < nch) { copy_chunk(ch + 1, cur ^ 1); CP_WAIT1(); }
        else              { CP_WAIT0(); }
        __syncthreads();
        compute(cur);
        __syncthreads();
    }

    #pragma unroll
    for (int mt = 0; mt < 2; mt++) {
        const int r0 = m0 + wy * 32 + mt * 16 + grp;
        #pragma unroll
        for (int nt = 0; nt < NT; nt++) {
            const int col = n0 + wx * WN + nt * 8 + 2 * ctg;
            float b0 = bias[col], b1 = bias[col + 1];
            float2 v0, v1;
            v0.x = acc[mt][nt][0] + b0; v0.y = acc[mt][nt][1] + b1;
            v1.x = acc[mt][nt][2] + b0; v1.y = acc[mt][nt][3] + b1;
            if (RELU) {
                v0.x = fmaxf(v0.x, 0.0f); v0.y = fmaxf(v0.y, 0.0f);
                v1.x = fmaxf(v1.x, 0.0f); v1.y = fmaxf(v1.y, 0.0f);
            }
            *(float2*)&C[(size_t)r0 * N + col] = v0;
            *(float2*)&C[(size_t)(r0 + 8) * N + col] = v1;
        }
    }
}

// ===========================================================================
// VQ kernel v2: tensor-core cross term (3xtf32), pre-split codebook.
// Block = (128 rows, group g). 8 chunks of 128 codewords, double-buffered.
// dist = zn - 2*cross + cn; per-thread argmin in MMA fragment layout,
// smem argmin reduction (tie -> lowest idx), gather z_q from fp32 codebook,
// fused deterministic loss reduction.
// Smem (floats): Zs 128*36 | CbB 2*128*36 | CbR 2*128*36 | CN 2*128 | zn 128 | lsum 128
// ===========================================================================
#define VQ_SMEM_FLOATS (4608 + 9216 + 9216 + 256 + 128 + 128)

__global__ __launch_bounds__(256, 2) void vq_kernel(
    const float* __restrict__ ze,
    const float* __restrict__ cb,
    const float* __restrict__ cbb,
    const float* __restrict__ cbr,
    const float* __restrict__ cn2,
    float* __restrict__ zq,
    float* __restrict__ idxf,
    float* __restrict__ losspart,
    float* __restrict__ lossout)
{
    extern __shared__ __align__(16) float sm[];
    float* Zs = sm;                                        // [128][36]
    float* CbB[2] = { sm + 4608, sm + 4608 + 4608 };
    float* CbR[2] = { sm + 13824, sm + 13824 + 4608 };
    float* CNs  = sm + 23040;                              // [2][128]
    float* zn   = sm + 23296;
    float* lsum = sm + 23424;

    const int tid = threadIdx.x;
    const int wid = tid >> 5;
    const int lane = tid & 31;
    const int grp = lane >> 2;
    const int ctg = lane & 3;
    const int wy  = wid & 3;
    const int wx  = wid >> 2;
    const int g    = blockIdx.y;
    const int row0 = blockIdx.x * 128;

    const float* zbase = ze  + (size_t)row0 * LATENT + g * GD;
    const float* cgb   = cb  + (size_t)g * KCB * GD;
    const float* cbbg  = cbb + (size_t)g * KCB * GD;
    const float* cbrg  = cbr + (size_t)g * KCB * GD;
    const float* cng   = cn2 + g * KCB;

    auto copyC = [&](int ch, int buf) {
        uint32_t sb_ = smem_u32(CbB[buf]);
        uint32_t sr_ = smem_u32(CbR[buf]);
        #pragma unroll
        for (int u = 0; u < 4; u++) {
            int f = tid + u * 256;
            int r = f >> 3, q = f & 7;
            size_t go = (size_t)(ch * 128 + r) * GD + q * 4;
            uint32_t so = (uint32_t)(r * 36 + q * 4) * 4;
            cp_async16(sb_ + so, cbbg + go);
            cp_async16(sr_ + so, cbrg + go);
        }
        if (tid < 32)
            cp_async16(smem_u32(CNs + buf * 128) + tid * 16, cng + ch * 128 + tid * 4);
    };

    // Prologue: Z tile + chunk0 (group 0), chunk1 (group 1)
    {
        uint32_t zs = smem_u32(Zs);
        #pragma unroll
        for (int u = 0; u < 4; u++) {
            int f = tid + u * 256;
            int r = f >> 3, q = f & 7;
            cp_async16(zs + (uint32_t)(r * 36 + q * 4) * 4,
                       zbase + (size_t)r * LATENT + q * 4);
        }
        copyC(0, 0);
        CP_COMMIT();
        copyC(1, 1);
        CP_COMMIT();
    }
    CP_WAIT1();
    __syncthreads();                 // Zs + chunk0 ready

    if (tid < 128) {
        float s = 0.0f;
        #pragma unroll
        for (int d = 0; d < 32; d++) { float z = Zs[tid * 36 + d]; s = fmaf(z, z, s); }
        zn[tid] = s;
    }
    __syncthreads();

    float znr[4];
    znr[0] = zn[wy * 32 + grp];
    znr[1] = zn[wy * 32 + 8 + grp];
    znr[2] = zn[wy * 32 + 16 + grp];
    znr[3] = zn[wy * 32 + 24 + grp];

    float best[4];
    int   bidx[4];
    #pragma unroll
    for (int i = 0; i < 4; i++) { best[i] = FLT_MAX; bidx[i] = 0; }

    int buf = 0;
    for (int ch = 0; ch < 8; ch++) {
        float acc[2][8][4];
        #pragma unroll
        for (int mt = 0; mt < 2; mt++)
            #pragma unroll
            for (int nt = 0; nt < 8; nt++)
                #pragma unroll
                for (int q = 0; q < 4; q++) acc[mt][nt][q] = 0.0f;

        const float* Bb_ = CbB[buf];
        const float* Br_ = CbR[buf];
        #pragma unroll
        for (int ks = 0; ks < 4; ks++) {
            const int k8 = ks * 8;
            uint32_t abig[2][4], ares[2][4];
            #pragma unroll
            for (int mt = 0; mt < 2; mt++) {
                const int rb = wy * 32 + mt * 16;
                float af[4];
                af[0] = Zs[(rb + grp) * 36 + k8 + ctg];
                af[1] = Zs[(rb + 8 + grp) * 36 + k8 + ctg];
                af[2] = Zs[(rb + grp) * 36 + k8 + 4 + ctg];
                af[3] = Zs[(rb + 8 + grp) * 36 + k8 + 4 + ctg];
                #pragma unroll
                for (int q = 0; q < 4; q++) {
                    abig[mt][q] = tf32_of(af[q]);
                    ares[mt][q] = tf32_of(af[q] - __uint_as_float(abig[mt][q]));
                }
            }
            #pragma unroll
            for (int nt = 0; nt < 8; nt++) {
                const int col = wx * 64 + nt * 8 + grp;
                uint32_t bb0 = __float_as_uint(Bb_[col * 36 + k8 + ctg]);
                uint32_t bb1 = __float_as_uint(Bb_[col * 36 + k8 + 4 + ctg]);
                uint32_t br0 = __float_as_uint(Br_[col * 36 + k8 + ctg]);
                uint32_t br1 = __float_as_uint(Br_[col * 36 + k8 + 4 + ctg]);
                #pragma unroll
                for (int mt = 0; mt < 2; mt++) {
                    mma_tf32(acc[mt][nt], abig[mt], bb0, bb1);
                    mma_tf32(acc[mt][nt], abig[mt], br0, br1);
                    mma_tf32(acc[mt][nt], ares[mt], bb0, bb1);
                }
            }
        }

        // Distance + argmin in fragment layout
        const float* CNc = CNs + buf * 128;
        #pragma unroll
        for (int nt = 0; nt < 8; nt++) {
            const int cbase = wx * 64 + nt * 8 + 2 * ctg;
            float cn0 = CNc[cbase], cn1 = CNc[cbase + 1];
            int   k0  = ch * 128 + cbase;
            #pragma unroll
            for (int mt = 0; mt < 2; mt++) {
                float d00 = znr[mt * 2 + 0] + fmaf(-2.0f, acc[mt][nt][0], cn0);
                float d01 = znr[mt * 2 + 0] + fmaf(-2.0f, acc[mt][nt][1], cn1);
                float d10 = znr[mt * 2 + 1] + fmaf(-2.0f, acc[mt][nt][2], cn0);
                float d11 = znr[mt * 2 + 1] + fmaf(-2.0f, acc[mt][nt][3], cn1);
                if (d00 < best[mt * 2])     { best[mt * 2] = d00;     bidx[mt * 2] = k0; }
                if (d01 < best[mt * 2])     { best[mt * 2] = d01;     bidx[mt * 2] = k0 + 1; }
                if (d10 < best[mt * 2 + 1]) { best[mt * 2 + 1] = d10; bidx[mt * 2 + 1] = k0; }
                if (d11 < best[mt * 2 + 1]) { best[mt * 2 + 1] = d11; bidx[mt * 2 + 1] = k0 + 1; }
            }
        }
        __syncthreads();                       // all warps done with buf
        if (ch + 2 < 8) { copyC(ch + 2, buf); CP_COMMIT(); }
        if (ch + 1 < 8) {
            if (ch + 2 < 8) CP_WAIT1(); else CP_WAIT0();
            __syncthreads();                   // chunk ch+1 visible to all
        }
        buf ^= 1;
    }

    // Cross-thread argmin reduction: per row 8 candidate slots (wx*4+ctg)
    float* redV = CbB[0];                      // 1024 floats
    int*   redI = (int*)(CbB[0] + 1024);       // 1024 ints (within 4608 region)
    #pragma unroll
    for (int s = 0; s < 4; s++) {
        int row = wy * 32 + (s >> 1) * 16 + (s & 1) * 8 + grp;
        redV[row * 8 + wx * 4 + ctg] = best[s];
        redI[row * 8 + wx * 4 + ctg] = bidx[s];
    }
    __syncthreads();

    if (tid < 128) {
        int   r  = tid;
        float bv = redV[r * 8];
        int   bi = redI[r * 8];
        #pragma unroll
        for (int t = 1; t < 8; t++) {
            float v  = redV[r * 8 + t];
            int   i2 = redI[r * 8 + t];
            if (v < bv || (v == bv && i2 < bi)) { bv = v; bi = i2; }
        }
        int grow = row0 + r;
        idxf[(size_t)grow * GRP + g] = (float)bi;

        const float* cw  = cgb + (size_t)bi * GD;
        float*       zqo = zq + (size_t)grow * LATENT + g * GD;
        float diff2 = 0.0f;
        #pragma unroll
        for (int dq = 0; dq < 8; dq++) {
            float4 c4 = *(const float4*)&cw[dq * 4];
            float d0 = c4.x - Zs[r * 36 + dq * 4 + 0];
            float d1 = c4.y - Zs[r * 36 + dq * 4 + 1];
            float d2 = c4.z - Zs[r * 36 + dq * 4 + 2];
            float d3 = c4.w - Zs[r * 36 + dq * 4 + 3];
            diff2 = fmaf(d0, d0, diff2);
            diff2 = fmaf(d1, d1, diff2);
            diff2 = fmaf(d2, d2, diff2);
            diff2 = fmaf(d3, d3, diff2);
            *(float4*)&zqo[dq * 4] = c4;
        }
        lsum[r] = diff2;
    }
    __syncthreads();

    __shared__ bool is_last;
    if (tid == 0) {
        float s = 0.0f;
        for (int r = 0; r < 128; r++) s += lsum[r];
        losspart[blockIdx.y * gridDim.x + blockIdx.x] = s;
        __threadfence();
        unsigned int t = atomicAdd(&g_cnt, 1u);
        is_last = (t == (unsigned int)(gridDim.x * gridDim.y - 1));
    }
    __syncthreads();

    if (is_last) {
        int npart = gridDim.x * gridDim.y;
        float v = 0.0f;
        for (int i = tid; i < npart; i += 256) v += losspart[i];
        redV[tid] = v;
        __syncthreads();
        for (int off = 128; off > 0; off >>= 1) {
            if (tid < off) redV[tid] += redV[tid + off];
            __syncthreads();
        }
        if (tid == 0) {
            lossout[0] = redV[0] * (1.0f / 1024000.0f);
            g_cnt = 0;
        }
    }
}

// ===========================================================================
extern "C" void kernel_launch(void* const* d_in, const int* in_sizes, int n_in,
                              void* d_out, int out_size)
{
    const float* bands = (const float*)d_in[0];
    const float* ew1   = (const float*)d_in[1];
    const float* eb1   = (const float*)d_in[2];
    const float* ew2   = (const float*)d_in[3];
    const float* eb2   = (const float*)d_in[4];
    const float* cb    = (const float*)d_in[5];
    const float* dw1   = (const float*)d_in[6];
    const float* db1   = (const float*)d_in[7];
    const float* dw2   = (const float*)d_in[8];
    const float* db2   = (const float*)d_in[9];

    float* out  = (float*)d_out;
    float* bhat = out;
    float* ze   = bhat + 1024000;
    float* zq   = ze   + 4096000;
    float* idxf = zq   + 4096000;
    float* loss = idxf + 128000;

    float* hid;   cudaGetSymbolAddress((void**)&hid,   g_hidden);
    float* lpart; cudaGetSymbolAddress((void**)&lpart, g_loss_part);
    float* wtb;   cudaGetSymbolAddress((void**)&wtb,   g_wtb);
    float* wtr;   cudaGetSymbolAddress((void**)&wtr,   g_wtr);
    float* cbb;   cudaGetSymbolAddress((void**)&cbb,   g_cbb);
    float* cbr;   cudaGetSymbolAddress((void**)&cbr,   g_cbr);
    float* cn2;   cudaGetSymbolAddress((void**)&cn2,   g_cn2);

    float* e1b = wtb;          float* e1r = wtr;
    float* e2b = wtb + 32768;  float* e2r = wtr + 32768;
    float* d1b = wtb + 163840; float* d1r = wtr + 163840;
    float* d2b = wtb + 294912; float* d2r = wtr + 294912;

    const int SM128 = (2 * 128 * 36 + 4 * 32 * 136) * 4;   // 106496
    const int SM64  = (2 * 128 * 36 + 4 * 32 * 72) * 4;    // 73728
    cudaFuncSetAttribute(tgemm<128, true >, cudaFuncAttributeMaxDynamicSharedMemorySize, SM128);
    cudaFuncSetAttribute(tgemm<128, false>, cudaFuncAttributeMaxDynamicSharedMemorySize, SM128);
    cudaFuncSetAttribute(tgemm<64,  false>, cudaFuncAttributeMaxDynamicSharedMemorySize, SM64);
    cudaFuncSetAttribute(vq_kernel, cudaFuncAttributeMaxDynamicSharedMemorySize, VQ_SMEM_FLOATS * 4);

    // One-time splits (per graph replay; cheap)
    wsplit<<<(32768 + 255) / 256, 256>>>(ew1, e1b, e1r, 32768);
    wsplit<<<(131072 + 255) / 256, 256>>>(ew2, e2b, e2r, 131072);
    wsplit<<<(131072 + 255) / 256, 256>>>(dw1, d1b, d1r, 131072);
    wsplit<<<(32768 + 255) / 256, 256>>>(dw2, d2b, d2r, 32768);
    csplit<<<(GRP * KCB + 255) / 256, 256>>>(cb, cbb, cbr, cn2);

    // Encoder
    tgemm<128, true ><<<dim3(HIDDEN / 128, NROWS / 128), 256, SM128>>>(
        bands, e1b, e1r, eb1, hid, NROWS, HIDDEN, NBANDS);
    tgemm<128, false><<<dim3(LATENT / 128, NROWS / 128), 256, SM128>>>(
        hid, e2b, e2r, eb2, ze, NROWS, LATENT, HIDDEN);

    // Vector quantization (tensor-core cross term + fused loss)
    vq_kernel<<<dim3(NROWS / 128, GRP), 256, VQ_SMEM_FLOATS * 4>>>(
        ze, cb, cbb, cbr, cn2, zq, idxf, lpart, loss);

    // Decoder
    tgemm<128, true ><<<dim3(HIDDEN / 128, NROWS / 128), 256, SM128>>>(
        zq, d1b, d1r, db1, hid, NROWS, HIDDEN, LATENT);
    tgemm<64,  false><<<dim3(NBANDS / 64, NROWS / 128), 256, SM64>>>(
        hid, d2b, d2r, db2, bhat, NROWS, NBANDS, HIDDEN);
}